// round 1
// baseline (speedup 1.0000x reference)
#include <cuda_runtime.h>
#include <cuda_bf16.h>

// ---------------------------------------------------------------------------
// Dimensions (fixed by the problem)
// ---------------------------------------------------------------------------
#define Bn    2
#define Hn    256
#define Wd    256
#define Cn    32
#define Pn    8
#define HEADS 8
#define DIMn  32
#define GH    32
#define GW    32
#define Mrows 2048            // B*GH*GW patches
#define K1    2048            // P*P*C
#define F1    16384           // DIM*P*P*HEADS
#define K2    16384           // P*P*HEADS*DIM
#define N2    2048            // DIM*P*P

// ---------------------------------------------------------------------------
// Device scratch (allocation-free rule: __device__ globals)
// ---------------------------------------------------------------------------
__device__ float g_A[Mrows * K1];              // patchified LN1(x)      16 MB
__device__ float g_q[Bn * HEADS * 1024 * DIMn * 64];   // 134 MB each
__device__ float g_k[Bn * HEADS * 1024 * DIMn * 64];
__device__ float g_v[Bn * HEADS * 1024 * DIMn * 64];
__device__ float g_o[Mrows * K2];              // im2col of gated output 134 MB

// ---------------------------------------------------------------------------
// Kernel 1: LN over channels + patchify into A matrix
//   A[(b,gh,gw)][(p0*8+p1)*32 + c] = LN1(x)[b, gh*8+p0, gw*8+p1, c]
// One warp per pixel (32 channels = 32 lanes).
// ---------------------------------------------------------------------------
__global__ __launch_bounds__(256)
void ln1_kernel(const float* __restrict__ x, const float* __restrict__ sc,
                const float* __restrict__ bi)
{
    int lane = threadIdx.x & 31;
    int warp = threadIdx.x >> 5;
    int pix  = blockIdx.x * 8 + warp;            // 0 .. B*H*W-1
    float v  = x[pix * 32 + lane];
    float su = v, sq = v * v;
#pragma unroll
    for (int off = 16; off; off >>= 1) {
        su += __shfl_xor_sync(0xffffffffu, su, off);
        sq += __shfl_xor_sync(0xffffffffu, sq, off);
    }
    float mu  = su * (1.f / 32.f);
    float var = sq * (1.f / 32.f) - mu * mu;
    float y   = (v - mu) * rsqrtf(var + 1e-6f) * sc[lane] + bi[lane];
    int b = pix >> 16;
    int h = (pix >> 8) & 255;
    int w = pix & 255;
    int row = b * 1024 + (h >> 3) * 32 + (w >> 3);
    g_A[row * K1 + ((h & 7) * 8 + (w & 7)) * 32 + lane] = y;
}

// ---------------------------------------------------------------------------
// SGEMM: C = A[M,K] * B[K,N] + bias, fused scatter epilogue.
//  EPI==0 : QKV projection. col f decodes (c,p0,p1,head); dest layout
//           [(b*8+head)*1024+ghgw][c][p0*8+p1]  (contiguous per patch-chan)
//  EPI==1 : output projection. col g decodes (c,p0,p1); dest is final
//           [B,H,W,DIM] with +bias +residual x.
// Tiling: 128x128x16, 256 threads, 8x8 per-thread microtile.
// All dims divide the tile sizes exactly -> no bounds checks.
// ---------------------------------------------------------------------------
template <int EPI>
__global__ __launch_bounds__(256, 2)
void sgemm_k(const float* __restrict__ A, const float* __restrict__ B,
             const float* __restrict__ bias, float* __restrict__ C,
             const float* __restrict__ X, int K, int N)
{
    __shared__ float As[16][132];
    __shared__ float Bs[16][132];

    const int tid = threadIdx.x;
    const int tx = tid & 15, ty = tid >> 4;
    const int rowBase = blockIdx.y * 128;
    const int colBase = blockIdx.x * 128;

    const int ar = tid >> 2;             // 0..63  (A tile row, +64 second)
    const int ak = (tid & 3) * 4;        // k offset within tile
    const int br = tid >> 5;             // 0..7   (B tile k-row, +8 second)
    const int bc = (tid & 31) * 4;       // col offset within tile

    const float* Ap = A + rowBase * K;
    const float* Bp = B + colBase;

    float acc[8][8];
#pragma unroll
    for (int i = 0; i < 8; i++)
#pragma unroll
        for (int j = 0; j < 8; j++) acc[i][j] = 0.f;

    for (int k0 = 0; k0 < K; k0 += 16) {
        float4 a0 = *(const float4*)&Ap[ar * K + k0 + ak];
        float4 a1 = *(const float4*)&Ap[(ar + 64) * K + k0 + ak];
        As[ak + 0][ar] = a0.x; As[ak + 1][ar] = a0.y;
        As[ak + 2][ar] = a0.z; As[ak + 3][ar] = a0.w;
        As[ak + 0][ar + 64] = a1.x; As[ak + 1][ar + 64] = a1.y;
        As[ak + 2][ar + 64] = a1.z; As[ak + 3][ar + 64] = a1.w;
        float4 b0 = *(const float4*)&Bp[(k0 + br) * N + bc];
        float4 b1 = *(const float4*)&Bp[(k0 + br + 8) * N + bc];
        *(float4*)&Bs[br][bc]     = b0;
        *(float4*)&Bs[br + 8][bc] = b1;
        __syncthreads();
#pragma unroll
        for (int kk = 0; kk < 16; kk++) {
            float a[8], b[8];
            *(float4*)&a[0] = *(const float4*)&As[kk][ty * 8];
            *(float4*)&a[4] = *(const float4*)&As[kk][ty * 8 + 4];
            *(float4*)&b[0] = *(const float4*)&Bs[kk][tx * 8];
            *(float4*)&b[4] = *(const float4*)&Bs[kk][tx * 8 + 4];
#pragma unroll
            for (int i = 0; i < 8; i++)
#pragma unroll
                for (int j = 0; j < 8; j++) acc[i][j] += a[i] * b[j];
        }
        __syncthreads();
    }

#pragma unroll
    for (int i = 0; i < 8; i++) {
        int r = rowBase + ty * 8 + i;
        int b_ = r >> 10, ghgw = r & 1023;
#pragma unroll
        for (int j = 0; j < 8; j++) {
            int f = colBase + tx * 8 + j;
            float v = acc[i][j] + bias[f];
            if (EPI == 0) {
                int head = f & 7, p1 = (f >> 3) & 7, p0 = (f >> 6) & 7, c = f >> 9;
                C[(((b_ * 8 + head) * 1024 + ghgw) * 32 + c) * 64 + p0 * 8 + p1] = v;
            } else {
                int gh = ghgw >> 5, gw = ghgw & 31;
                int p1 = f & 7, p0 = (f >> 3) & 7, c = f >> 6;
                int idx = ((b_ * 256 + gh * 8 + p0) * 256 + gw * 8 + p1) * 32 + c;
                C[idx] = v + X[idx];
            }
        }
    }
}

// ---------------------------------------------------------------------------
// Kernel 3: fused 8x8 circular conv (== irfft2(rfft2(q)*rfft2(k)))
//           + LN2 over DIM + gate by V + scatter into im2col of out-proj.
// One block per (b,head,gh,gw): 32 channels x 64 positions.
// Thread layout: warp = p0 (8 warps), lane = c (32 lanes).
// ---------------------------------------------------------------------------
__global__ __launch_bounds__(256)
void fsas_kernel(const float* __restrict__ ln2s, const float* __restrict__ ln2b)
{
    __shared__ float sq[32][65], sk[32][65], sv[32][65], so[32][65];
    __shared__ float smu[64], srv[64];

    int tid  = threadIdx.x;
    int blk  = blockIdx.x;                  // (b*8+head)*1024 + ghgw
    int bh   = blk >> 10, ghgw = blk & 1023;
    int b    = bh >> 3,   head = bh & 7;
    int base = blk * 2048;

    for (int i = tid; i < 2048; i += 256) {
        int c = i >> 6, p = i & 63;
        sq[c][p] = g_q[base + i];
        sk[c][p] = g_k[base + i];
        sv[c][p] = g_v[base + i];
    }
    __syncthreads();

    int c = tid & 31, p0 = tid >> 5;
    float out[8] = {0.f, 0.f, 0.f, 0.f, 0.f, 0.f, 0.f, 0.f};
#pragma unroll
    for (int a0 = 0; a0 < 8; a0++) {
        const float* qr = &sq[c][a0 * 8];
        const float* kr = &sk[c][((p0 - a0) & 7) * 8];
        float kv[8];
#pragma unroll
        for (int t = 0; t < 8; t++) kv[t] = kr[t];
#pragma unroll
        for (int a1 = 0; a1 < 8; a1++) {
            float qa = qr[a1];
#pragma unroll
            for (int p1 = 0; p1 < 8; p1++) out[p1] += qa * kv[(p1 - a1) & 7];
        }
    }
#pragma unroll
    for (int p1 = 0; p1 < 8; p1++) so[c][p0 * 8 + p1] = out[p1];
    __syncthreads();

    if (tid < 64) {                          // LN stats per position over c
        float s = 0.f, s2 = 0.f;
#pragma unroll
        for (int cc = 0; cc < 32; cc++) { float v = so[cc][tid]; s += v; s2 += v * v; }
        float mu  = s * (1.f / 32.f);
        float var = s2 * (1.f / 32.f) - mu * mu;
        smu[tid] = mu;
        srv[tid] = rsqrtf(var + 1e-6f);
    }
    __syncthreads();

    int orow = (b * 1024 + ghgw) * K2 + head * 32;
    for (int i = tid; i < 2048; i += 256) {
        int p = i >> 5, cc = i & 31;
        float val = (so[cc][p] - smu[p]) * srv[p] * ln2s[cc] + ln2b[cc];
        val *= sv[cc][p];
        g_o[orow + p * 256 + cc] = val;      // im2col layout for out-proj GEMM
    }
}

// ---------------------------------------------------------------------------
// Launch
// ---------------------------------------------------------------------------
extern "C" void kernel_launch(void* const* d_in, const int* in_sizes, int n_in,
                              void* d_out, int out_size)
{
    const float* x    = (const float*)d_in[0];
    const float* ln1s = (const float*)d_in[1];
    const float* ln1b = (const float*)d_in[2];
    const float* Wq   = (const float*)d_in[3];
    const float* bq   = (const float*)d_in[4];
    const float* Wk   = (const float*)d_in[5];
    const float* bk   = (const float*)d_in[6];
    const float* Wv   = (const float*)d_in[7];
    const float* bv   = (const float*)d_in[8];
    const float* ln2s = (const float*)d_in[9];
    const float* ln2b = (const float*)d_in[10];
    const float* Wo   = (const float*)d_in[11];
    const float* bo   = (const float*)d_in[12];
    float* out = (float*)d_out;

    float *pA, *pq, *pk, *pv, *po;
    cudaGetSymbolAddress((void**)&pA, g_A);
    cudaGetSymbolAddress((void**)&pq, g_q);
    cudaGetSymbolAddress((void**)&pk, g_k);
    cudaGetSymbolAddress((void**)&pv, g_v);
    cudaGetSymbolAddress((void**)&po, g_o);

    // 1) LN1 + patchify
    ln1_kernel<<<(Bn * Hn * Wd) / 8, 256>>>(x, ln1s, ln1b);

    // 2) Q/K/V projections: [2048x2048] x [2048x16384]
    dim3 g1(F1 / 128, Mrows / 128);
    sgemm_k<0><<<g1, 256>>>(pA, Wq, bq, pq, nullptr, K1, F1);
    sgemm_k<0><<<g1, 256>>>(pA, Wk, bk, pk, nullptr, K1, F1);
    sgemm_k<0><<<g1, 256>>>(pA, Wv, bv, pv, nullptr, K1, F1);

    // 3) circular conv + LN2 + gate + im2col
    fsas_kernel<<<Bn * HEADS * GH * GW, 256>>>(ln2s, ln2b);

    // 4) output projection + bias + residual: [2048x16384] x [16384x2048]
    dim3 g2(N2 / 128, Mrows / 128);
    sgemm_k<1><<<g2, 256>>>(po, Wo, bo, out, x, K2, N2);
}